// round 17
// baseline (speedup 1.0000x reference)
#include <cuda_runtime.h>
#include <cuda_fp16.h>
#include <cstdint>

#define BB 8
#define CC 16
#define FDIM 256
#define F2 129
#define TT 512
#define C2 32
#define HH 16
#define NT (BB*TT)

// ---------------- device scratch ----------------
__device__ float g_zraw[(size_t)BB*C2*F2*TT];   // spectrum planes (b, c2, k, t): re c=0..15, im c=16..31
__device__ __half g_pre16[(size_t)NT*F2*128];   // fp16 gate preacts, PERMUTED: pos 2m/2m+1 = rows m/m+32 per dir
__device__ float g_h   [(size_t)NT*F2*C2];      // LSTM hidden cat(fwd,bwd): (n, k, 2H)
__device__ float4 g_P4 [(size_t)BB*16*F2*256];  // packed product spectra: (b,c,k,tpair) = (zr,zi,wr,wi)
__device__ float g_mean[NT];
__device__ float g_rstd[NT];
__device__ float g_psum[NT*16];
__device__ float g_psq [NT*16];

__device__ __forceinline__ float tanha(float x) {
    float r;
    asm("tanh.approx.f32 %0, %1;" : "=f"(r) : "f"(x));
    return r;
}
__device__ __forceinline__ unsigned int f2tf32(float f) {
    unsigned int r;
    asm("cvt.rna.tf32.f32 %0, %1;" : "=r"(r) : "f"(f));
    return r;
}
__device__ __forceinline__ void mma_tf32(float* d,
    unsigned int a0, unsigned int a1, unsigned int a2, unsigned int a3,
    unsigned int b0, unsigned int b1) {
    asm volatile(
        "mma.sync.aligned.m16n8k8.row.col.f32.tf32.tf32.f32 "
        "{%0,%1,%2,%3}, {%4,%5,%6,%7}, {%8,%9}, {%0,%1,%2,%3};"
        : "+f"(d[0]), "+f"(d[1]), "+f"(d[2]), "+f"(d[3])
        : "r"(a0), "r"(a1), "r"(a2), "r"(a3), "r"(b0), "r"(b1));
}
__device__ __forceinline__ int dr4(int k) {
    return ((k & 3) << 6) | (((k >> 2) & 3) << 4) | (((k >> 4) & 3) << 2) | ((k >> 6) & 3);
}

// ---------------- K1: forward rfft + fused norm-stat partials ----------------
__global__ void __launch_bounds__(512) k_fft_fwd(const float* __restrict__ x) {
    int bc = blockIdx.x;
    int t0 = blockIdx.y * 32;
    int b = bc >> 4, c = bc & 15;
    __shared__ float sr[258][17], si[258][17];
    __shared__ float2 tw[192];
    int tid = threadIdx.x;
    int w = tid >> 5, l = tid & 31;

    if (tid < 192) {
        float sv, cv;
        __sincosf(-6.28318530717958647692f * (float)tid * (1.f / 256.f), &sv, &cv);
        tw[tid] = make_float2(cv, sv);
    }
    for (int i = tid; i < 8192; i += 512) {
        int f = i >> 5, tt = i & 31;
        float v = x[((size_t)bc * 256 + f) * 512 + t0 + tt];
        if (tt & 1) si[f][tt >> 1] = v; else sr[f][tt >> 1] = v;
    }
    __syncthreads();

    #pragma unroll
    for (int stage = 0; stage < 4; ++stage) {
        int ms = 6 - 2 * stage;
        int m = 1 << ms;
        #pragma unroll
        for (int half = 0; half < 2; ++half) {
            int bfy = l + 32 * half;
            int g = bfy >> ms, p = bfy & (m - 1);
            int base = (g << (ms + 2)) + p;
            int e1 = p << (2 * stage);
            float2 w1 = tw[e1], w2 = tw[2 * e1], w3 = tw[3 * e1];
            float ar = sr[base][w],        ai = si[base][w];
            float br = sr[base + m][w],    bi = si[base + m][w];
            float cr = sr[base + 2*m][w],  ci = si[base + 2*m][w];
            float dr = sr[base + 3*m][w],  di = si[base + 3*m][w];
            float t0r = ar + cr, t0i = ai + ci;
            float t1r = ar - cr, t1i = ai - ci;
            float t2r = br + dr, t2i = bi + di;
            float t3r = br - dr, t3i = bi - di;
            sr[base][w] = t0r + t2r;  si[base][w] = t0i + t2i;
            float u1r = t1r + t3i, u1i = t1i - t3r;
            sr[base + m][w]   = u1r * w1.x - u1i * w1.y;
            si[base + m][w]   = u1r * w1.y + u1i * w1.x;
            float v2r = t0r - t2r, v2i = t0i - t2i;
            sr[base + 2*m][w] = v2r * w2.x - v2i * w2.y;
            si[base + 2*m][w] = v2r * w2.y + v2i * w2.x;
            float u3r = t1r - t3i, u3i = t1i + t3r;
            sr[base + 3*m][w] = u3r * w3.x - u3i * w3.y;
            si[base + 3*m][w] = u3r * w3.y + u3i * w3.x;
        }
        __syncwarp();
    }

    float va[5][4];
    #pragma unroll
    for (int r = 0; r < 4; ++r) {
        int k = l + 32 * r;
        int ik = dr4(k), im = dr4((256 - k) & 255);
        float zkr = sr[ik][w], zki = si[ik][w];
        float zmr = sr[im][w], zmi = si[im][w];
        va[r][0] = 0.5f * (zkr + zmr);
        va[r][1] = 0.5f * (zki - zmi);
        va[r][2] = 0.5f * (zki + zmi);
        va[r][3] = 0.5f * (zmr - zkr);
    }
    if (l == 0) {
        int ik = dr4(128);
        float zkr = sr[ik][w], zki = si[ik][w];
        va[4][0] = zkr; va[4][1] = 0.f;
        va[4][2] = zki; va[4][3] = 0.f;
    }

    {
        float sA = 0.f, qA = 0.f, sB = 0.f, qB = 0.f;
        #pragma unroll
        for (int r = 0; r < 4; ++r) {
            sA += va[r][0] + va[r][1];
            qA = fmaf(va[r][0], va[r][0], qA); qA = fmaf(va[r][1], va[r][1], qA);
            sB += va[r][2] + va[r][3];
            qB = fmaf(va[r][2], va[r][2], qB); qB = fmaf(va[r][3], va[r][3], qB);
        }
        if (l == 0) {
            sA += va[4][0] + va[4][1];
            qA = fmaf(va[4][0], va[4][0], qA); qA = fmaf(va[4][1], va[4][1], qA);
            sB += va[4][2] + va[4][3];
            qB = fmaf(va[4][2], va[4][2], qB); qB = fmaf(va[4][3], va[4][3], qB);
        }
        #pragma unroll
        for (int off = 16; off; off >>= 1) {
            sA += __shfl_xor_sync(0xffffffffu, sA, off);
            qA += __shfl_xor_sync(0xffffffffu, qA, off);
            sB += __shfl_xor_sync(0xffffffffu, sB, off);
            qB += __shfl_xor_sync(0xffffffffu, qB, off);
        }
        if (l == 0) {
            int nA = b * 512 + t0 + 2 * w;
            g_psum[nA * 16 + c] = sA;       g_psq[nA * 16 + c] = qA;
            g_psum[(nA + 1) * 16 + c] = sB; g_psq[(nA + 1) * 16 + c] = qB;
        }
    }

    __syncwarp();
    #pragma unroll
    for (int r = 0; r < 4; ++r) {
        int k = l + 32 * r;
        sr[k][w] = va[r][0];        si[k][w] = va[r][1];
        sr[129 + k][w] = va[r][2];  si[129 + k][w] = va[r][3];
    }
    if (l == 0) {
        sr[128][w] = va[4][0];       si[128][w] = va[4][1];
        sr[129 + 128][w] = va[4][2]; si[129 + 128][w] = va[4][3];
    }
    __syncthreads();

    for (int i = tid; i < 4128; i += 512) {
        int k = i >> 5, tt = i & 31;
        int j = tt >> 1;
        int row = (tt & 1) ? (129 + k) : k;
        g_zraw[(((size_t)b * 32 + c)      * 129 + k) * 512 + t0 + tt] = sr[row][j];
        g_zraw[(((size_t)b * 32 + 16 + c) * 129 + k) * 512 + t0 + tt] = si[row][j];
    }
}

// ---------------- K2: finalize stats ----------------------------------------
__global__ void k_stats2() {
    int n = blockIdx.x * 256 + threadIdx.x;
    float S = 0.f, Q = 0.f;
    #pragma unroll
    for (int p = 0; p < 16; ++p) { S += g_psum[n * 16 + p]; Q += g_psq[n * 16 + p]; }
    float mean = S * (1.f / 4128.f);
    float var = (Q - S * mean) * (1.f / 4127.f);
    g_mean[n] = mean;
    g_rstd[n] = __fdividef(1.f, sqrtf(fmaxf(var, 0.f)) + 1e-8f);
}

// ---------------- K3: gate GEMM, normalize folded into load -----------------
__global__ void __launch_bounds__(256) k_gates(
    const float* __restrict__ nw, const float* __restrict__ nb,
    const float* __restrict__ wihf, const float* __restrict__ bihf, const float* __restrict__ bhhf,
    const float* __restrict__ wihb, const float* __restrict__ bihb, const float* __restrict__ bhhb) {
    int k = blockIdx.x;
    int n0 = blockIdx.y * 64;
    int b = n0 >> 9, tl0 = n0 & 511;
    __shared__ unsigned int ys[32][72];
    __shared__ __align__(16) union {
        unsigned int w[128][36];
        __half stage[64][136];
    } u;
    __shared__ float nws[32], nbs[32], means[64], rstds[64], bs[128];
    int tid = threadIdx.x;

    // phase 1: small params
    if (tid < 32) { nws[tid] = nw[tid * 129 + k]; nbs[tid] = nb[tid * 129 + k]; }
    if (tid >= 64 && tid < 128) { means[tid - 64] = g_mean[n0 + tid - 64]; rstds[tid - 64] = g_rstd[n0 + tid - 64]; }
    if (tid >= 128) {
        int gi = tid - 128;
        int dir = gi >> 6, nn = gi & 63;
        int row = ((nn & 1) << 5) + (nn >> 1);
        bs[gi] = dir ? (bihb[row] + bhhb[row]) : (bihf[row] + bhhf[row]);
    }
    __syncthreads();

    // phase 2: z load + normalize + tf32 in one pass; weights load
    for (int i = tid; i < 2048; i += 256) {
        int c2 = i >> 6, tt = i & 63;
        float zz = g_zraw[(((size_t)b * 32 + c2) * 129 + k) * 512 + tl0 + tt];
        float v = (zz - means[tt]) * rstds[tt] * nws[c2] + nbs[c2];
        ys[c2][tt] = f2tf32(v);
    }
    for (int i = tid; i < 4096; i += 256) {
        int n = i >> 5, q = i & 31;
        int dir = n >> 6, nn = n & 63;
        int row = ((nn & 1) << 5) + (nn >> 1);
        float wv = dir ? wihb[row * 32 + q] : wihf[row * 32 + q];
        u.w[n][q] = f2tf32(wv);
    }
    __syncthreads();

    int wid = tid >> 5, lane = tid & 31;
    int gid = lane >> 2, tid4 = lane & 3;
    int m_base = (wid & 3) << 4;
    int n_base0 = (wid >> 2) << 6;

    float acc[8][4];
    #pragma unroll
    for (int j = 0; j < 8; ++j) {
        int gb = n_base0 + j * 8 + tid4 * 2;
        acc[j][0] = bs[gb];     acc[j][1] = bs[gb + 1];
        acc[j][2] = bs[gb];     acc[j][3] = bs[gb + 1];
    }

    #pragma unroll
    for (int ks = 0; ks < 32; ks += 8) {
        unsigned int a0 = ys[ks + tid4    ][m_base + gid];
        unsigned int a1 = ys[ks + tid4    ][m_base + gid + 8];
        unsigned int a2 = ys[ks + tid4 + 4][m_base + gid];
        unsigned int a3 = ys[ks + tid4 + 4][m_base + gid + 8];
        #pragma unroll
        for (int j = 0; j < 8; ++j) {
            int gb = n_base0 + j * 8 + gid;
            unsigned int b0 = u.w[gb][ks + tid4];
            unsigned int b1 = u.w[gb][ks + tid4 + 4];
            mma_tf32(acc[j], a0, a1, a2, a3, b0, b1);
        }
    }
    __syncthreads();

    #pragma unroll
    for (int j = 0; j < 8; ++j) {
        int pos = n_base0 + j * 8 + tid4 * 2;
        int r0 = m_base + gid;
        __half2 v0 = __floats2half2_rn(acc[j][0], acc[j][1]);
        __half2 v1 = __floats2half2_rn(acc[j][2], acc[j][3]);
        *reinterpret_cast<__half2*>(&u.stage[r0][pos]) = v0;
        *reinterpret_cast<__half2*>(&u.stage[r0 + 8][pos]) = v1;
    }
    __syncthreads();

    for (int i = tid; i < 1024; i += 256) {
        int row = i >> 4, q4 = i & 15;
        uint4 v = *reinterpret_cast<const uint4*>(&u.stage[row][q4 * 8]);
        *reinterpret_cast<uint4*>(&g_pre16[((size_t)(n0 + row) * 129 + k) * 128 + q4 * 8]) = v;
    }
}

// ---------------- K4: recurrent-only LSTM, tanh.approx activations ----------
__global__ void __launch_bounds__(256) k_lstm(
    const float* __restrict__ whhf, const float* __restrict__ whhb) {
    int wg = blockIdx.x * 8 + (threadIdx.x >> 5);
    int lane = threadIdx.x & 31;
    int n = wg >> 1, dir = wg & 1;

    const float* whh = dir ? whhb : whhf;
    float wh0[16], wh1[16];
    #pragma unroll
    for (int q = 0; q < 16; ++q) {
        wh0[q] = whh[lane * 16 + q];
        wh1[q] = whh[(lane + 32) * 16 + q];
    }
    // act1 params: lane<16 -> tanh (s=1, c=0); lane>=16 -> sigmoid (s=0.5, c=0.5)
    float s1 = (lane < 16) ? 1.f : 0.5f;
    float c1 = (lane < 16) ? 0.f : 0.5f;

    const __half2* pbase2 = reinterpret_cast<const __half2*>(g_pre16 + (size_t)n * 129 * 128) + dir * 32 + lane;
    float* hbase = g_h + (size_t)n * 129 * 32 + dir * 16;

    float h = 0.f, cst = 0.f;
    int k = dir ? 128 : 0;
    int stepd = dir ? -1 : 1;
    float2 p = __half22float2(pbase2[k * 64]);

    #pragma unroll 2
    for (int s = 0; s < 129; ++s) {
        int kn = k + stepd;
        float2 np = make_float2(0.f, 0.f);
        if (s < 128) np = __half22float2(pbase2[kn * 64]);
        float a0 = p.x, a1 = p.y, c0 = 0.f, cc1 = 0.f;
        #pragma unroll
        for (int q = 0; q < 8; ++q) {
            float hv = __shfl_sync(0xffffffffu, h, q);
            a0 = fmaf(hv, wh0[q], a0);
            a1 = fmaf(hv, wh1[q], a1);
        }
        #pragma unroll
        for (int q = 8; q < 16; ++q) {
            float hv = __shfl_sync(0xffffffffu, h, q);
            c0 = fmaf(hv, wh0[q], c0);
            cc1 = fmaf(hv, wh1[q], cc1);
        }
        a0 += c0; a1 += cc1;
        // act0 = sigmoid(a0) ; act1 = tanh(a1) [lane<16] / sigmoid(a1)
        float act0 = fmaf(0.5f, tanha(0.5f * a0), 0.5f);
        float act1 = fmaf(s1, tanha(s1 * a1), c1);
        float fa = __shfl_xor_sync(0xffffffffu, act0, 16);
        float oa = __shfl_xor_sync(0xffffffffu, act1, 16);
        if (lane < 16) {
            cst = fmaf(fa, cst, act0 * act1);
            h = oa * tanha(cst);
            hbase[k * 32 + lane] = h;
        }
        p = np; k = kn;
    }
}

// ---------------- K5: linear(2H->2C) + cmul, packed-Z float4 output ---------
__global__ void __launch_bounds__(256) k_lin_cmul(const float* __restrict__ lw, const float* __restrict__ lb) {
    int k = blockIdx.x, t0 = blockIdx.y * 64, b = blockIdx.z;
    __shared__ __align__(16) float hs[32][68];     // [j][t]
    __shared__ __align__(16) float lws[32][34];    // [j][c2]
    __shared__ float lbs[32];
    __shared__ __align__(16) float yls[32][68];    // [c2][t]
    int tid = threadIdx.x;

    for (int i = tid; i < 2048; i += 256) {
        int tt = i >> 5, j = i & 31;
        hs[j][tt] = g_h[(((size_t)(b * 512 + t0 + tt)) * 129 + k) * 32 + j];
    }
    for (int i = tid; i < 1024; i += 256) {
        int c2 = i >> 5, j = i & 31;
        lws[j][c2] = lw[c2 * 32 + j];
    }
    if (tid < 32) lbs[tid] = lb[tid];
    __syncthreads();

    int tg = tid & 15, cg = tid >> 4;
    int t4 = tg << 2, c22 = cg << 1;
    float acc[2][4];
    #pragma unroll
    for (int t = 0; t < 4; ++t) { acc[0][t] = lbs[c22]; acc[1][t] = lbs[c22 + 1]; }
    #pragma unroll 4
    for (int j = 0; j < 32; ++j) {
        float4 hv = *reinterpret_cast<const float4*>(&hs[j][t4]);
        float2 wv = *reinterpret_cast<const float2*>(&lws[j][c22]);
        acc[0][0] = fmaf(hv.x, wv.x, acc[0][0]);
        acc[0][1] = fmaf(hv.y, wv.x, acc[0][1]);
        acc[0][2] = fmaf(hv.z, wv.x, acc[0][2]);
        acc[0][3] = fmaf(hv.w, wv.x, acc[0][3]);
        acc[1][0] = fmaf(hv.x, wv.y, acc[1][0]);
        acc[1][1] = fmaf(hv.y, wv.y, acc[1][1]);
        acc[1][2] = fmaf(hv.z, wv.y, acc[1][2]);
        acc[1][3] = fmaf(hv.w, wv.y, acc[1][3]);
    }
    #pragma unroll
    for (int t = 0; t < 4; ++t) {
        yls[c22][t4 + t] = acc[0][t];
        yls[c22 + 1][t4 + t] = acc[1][t];
    }
    __syncthreads();

    bool edge = (k == 0) | (k == 128);
    for (int i = tid; i < 512; i += 256) {
        int c = i >> 5, tp = i & 31;
        int t2 = tp * 2;
        float2 xr2 = *reinterpret_cast<const float2*>(&g_zraw[(((size_t)b * 32 + c) * 129 + k) * 512 + t0 + t2]);
        float2 xi2 = *reinterpret_cast<const float2*>(&g_zraw[(((size_t)b * 32 + 16 + c) * 129 + k) * 512 + t0 + t2]);
        float2 yr = *reinterpret_cast<const float2*>(&yls[c][t2]);
        float2 yi = *reinterpret_cast<const float2*>(&yls[c + 16][t2]);
        float par = yr.x * xr2.x - yi.x * xi2.x;
        float pai = yr.x * xi2.x + yi.x * xr2.x;
        float pbr = yr.y * xr2.y - yi.y * xi2.y;
        float pbi = yr.y * xi2.y + yi.y * xr2.y;
        if (edge) { pai = 0.f; pbi = 0.f; }
        float4 v = make_float4(par - pbi, pai + pbr, par + pbi, pbr - pai);
        g_P4[((size_t)(b * 16 + c) * 129 + k) * 256 + (t0 >> 1) + tp] = v;
    }
}

// ---------------- K6: irfft from packed-Z float4 ----------------------------
__global__ void __launch_bounds__(512) k_fft_inv(float* __restrict__ out) {
    int bc = blockIdx.x;
    int t0 = blockIdx.y * 32;
    int b = bc >> 4, c = bc & 15;
    __shared__ float sr[258][17], si[258][17];
    __shared__ float2 tw[192];
    int tid = threadIdx.x;
    int w = tid >> 5, l = tid & 31;

    if (tid < 192) {
        float sv, cv;
        __sincosf(6.28318530717958647692f * (float)tid * (1.f / 256.f), &sv, &cv);
        tw[tid] = make_float2(cv, sv);
    }
    const float4* pb4 = g_P4 + (size_t)(b * 16 + c) * 129 * 256 + (t0 >> 1);
    for (int i = tid; i < 2064; i += 512) {
        int k = i >> 4, j = i & 15;
        float4 v = pb4[(size_t)k * 256 + j];
        sr[k][j] = v.x; si[k][j] = v.y;
        if (k >= 1 && k <= 127) {
            sr[256 - k][j] = v.z; si[256 - k][j] = v.w;
        }
    }
    __syncthreads();

    #pragma unroll
    for (int stage = 0; stage < 4; ++stage) {
        int ms = 6 - 2 * stage;
        int m = 1 << ms;
        #pragma unroll
        for (int half = 0; half < 2; ++half) {
            int bfy = l + 32 * half;
            int g = bfy >> ms, p = bfy & (m - 1);
            int base = (g << (ms + 2)) + p;
            int e1 = p << (2 * stage);
            float2 w1 = tw[e1], w2 = tw[2 * e1], w3 = tw[3 * e1];
            float ar = sr[base][w],        ai = si[base][w];
            float br = sr[base + m][w],    bi = si[base + m][w];
            float cr = sr[base + 2*m][w],  ci = si[base + 2*m][w];
            float dr = sr[base + 3*m][w],  di = si[base + 3*m][w];
            float t0r = ar + cr, t0i = ai + ci;
            float t1r = ar - cr, t1i = ai - ci;
            float t2r = br + dr, t2i = bi + di;
            float t3r = br - dr, t3i = bi - di;
            sr[base][w] = t0r + t2r;  si[base][w] = t0i + t2i;
            float u1r = t1r - t3i, u1i = t1i + t3r;
            sr[base + m][w]   = u1r * w1.x - u1i * w1.y;
            si[base + m][w]   = u1r * w1.y + u1i * w1.x;
            float v2r = t0r - t2r, v2i = t0i - t2i;
            sr[base + 2*m][w] = v2r * w2.x - v2i * w2.y;
            si[base + 2*m][w] = v2r * w2.y + v2i * w2.x;
            float u3r = t1r + t3i, u3i = t1i - t3r;
            sr[base + 3*m][w] = u3r * w3.x - u3i * w3.y;
            si[base + 3*m][w] = u3r * w3.y + u3i * w3.x;
        }
        __syncwarp();
    }
    __syncthreads();

    const float inv = 1.f / 256.f;
    for (int i = tid; i < 8192; i += 512) {
        int f = i >> 5, tt = i & 31;
        int j = tt >> 1;
        int src = dr4(f);
        float v = (tt & 1) ? si[src][j] : sr[src][j];
        out[((size_t)bc * 256 + f) * 512 + t0 + tt] = v * inv;
    }
}

// ---------------- launcher ---------------------------------------------------
extern "C" void kernel_launch(void* const* d_in, const int* in_sizes, int n_in,
                              void* d_out, int out_size) {
    const float* x    = (const float*)d_in[0];
    const float* nw   = (const float*)d_in[1];
    const float* nb   = (const float*)d_in[2];
    const float* wihf = (const float*)d_in[3];
    const float* whhf = (const float*)d_in[4];
    const float* bihf = (const float*)d_in[5];
    const float* bhhf = (const float*)d_in[6];
    const float* wihb = (const float*)d_in[7];
    const float* whhb = (const float*)d_in[8];
    const float* bihb = (const float*)d_in[9];
    const float* bhhb = (const float*)d_in[10];
    const float* lw   = (const float*)d_in[11];
    const float* lb   = (const float*)d_in[12];
    float* out = (float*)d_out;

    k_fft_fwd<<<dim3(128, 16), 512>>>(x);
    k_stats2<<<16, 256>>>();
    k_gates<<<dim3(129, 64), 256>>>(nw, nb, wihf, bihf, bhhf, wihb, bihb, bhhb);
    k_lstm<<<1024, 256>>>(whhf, whhb);
    k_lin_cmul<<<dim3(129, 8, 8), 256>>>(lw, lb);
    k_fft_inv<<<dim3(128, 16), 512>>>(out);
}